// round 8
// baseline (speedup 1.0000x reference)
#include <cuda_runtime.h>
#include <cuda_bf16.h>

// Problem constants (fixed by the reference)
#define Cc    8
#define Ll    4096
#define Ff    32
#define Kk    10
#define PROC  20
#define STEP  5
#define NWIN  815          // == CHAN_OUT, no pad region
#define WPB   256          // threads per block
#define WINPB 512          // windows per block (2 per thread, adjacent)
#define NTILE 2            // ceil(815/512)

// Shared x tile: covers WINPB windows -> WINPB*STEP + (PROC-STEP) = 2575 floats
#define SXN (WINPB * STEP + PROC - STEP)

// Exact 3-way float min for NONNEGATIVE floats via DPX VIMNMX3:
// IEEE nonneg floats order identically to their int bit patterns.
__device__ __forceinline__ float fmin3_nonneg(float a, float b, float c)
{
    return __int_as_float(__vimin3_s32(__float_as_int(a),
                                       __float_as_int(b),
                                       __float_as_int(c)));
}

__global__ __launch_bounds__(WPB, 2)
void dtw_kernel(const float* __restrict__ x,
                const float* __restrict__ kernels,
                float* __restrict__ out)
{
    const int tile = blockIdx.x;          // window tile [0, NTILE)
    const int f    = blockIdx.y;          // filter     [0, Ff)
    const int bc   = blockIdx.z;          // b*C + c    [0, 64)
    const int tid  = threadIdx.x;

    __shared__ float sx[SXN];

    // Cooperative, coalesced load of the x tile for this (b,c)
    const int    base = tile * WINPB * STEP;
    const float* xc   = x + (size_t)bc * Ll;
    #pragma unroll
    for (int i = tid; i < SXN; i += WPB) {
        int g = base + i;
        sx[i] = (g < Ll) ? xc[g] : 0.0f;
    }
    __syncthreads();

    // This thread owns adjacent windows g0 = tile*512 + 2*tid and g0+1.
    const int g0 = tile * WINPB + 2 * tid;
    if (g0 >= NWIN) return;               // no syncs below: divergence-safe

    // Kernel taps: warp-uniform addresses -> broadcast loads, L1-resident
    float ker[Kk];
    #pragma unroll
    for (int i = 0; i < Kk; i++) ker[i] = __ldg(&kernels[f * Kk + i]);

    // 25-float span covers BOTH windows: w0[j] = s[j], w1[j] = s[j+5].
    float s[PROC + STEP];
    #pragma unroll
    for (int j = 0; j < PROC + STEP; j++) s[j] = sx[2 * tid * STEP + j];

    // Two independent DTW tables, interleaved for ILP=2. Fully unrolled:
    // register renaming kills all rotation MOVs.
    float a0[PROC], a1[PROC];

    // Row 0: cumulative sum of squared diffs
    {
        const float k0 = ker[0];
        float d0 = k0 - s[0];
        float d1 = k0 - s[STEP];
        a0[0] = d0 * d0;
        a1[0] = d1 * d1;
        #pragma unroll
        for (int j = 1; j < PROC; j++) {
            d0 = k0 - s[j];
            d1 = k0 - s[j + STEP];
            a0[j] = fmaf(d0, d0, a0[j - 1]);
            a1[j] = fmaf(d1, d1, a1[j - 1]);
        }
    }

    // Rows 1..K-1. One VIMNMX3 (DPX) replaces both FMNMX per cell; values are
    // all >= 0 (sums of squares) so int-ordered min is exact.
    #pragma unroll
    for (int i = 1; i < Kk; i++) {
        const float kv = ker[i];
        float dg0 = a0[0];
        float dg1 = a1[0];
        float d0 = kv - s[0];
        float d1 = kv - s[STEP];
        a0[0] = fmaf(d0, d0, a0[0]);
        a1[0] = fmaf(d1, d1, a1[0]);
        #pragma unroll
        for (int j = 1; j < PROC; j++) {
            const float up0 = a0[j];
            const float up1 = a1[j];
            const float m0  = fmin3_nonneg(a0[j - 1], up0, dg0);
            const float m1  = fmin3_nonneg(a1[j - 1], up1, dg1);
            d0 = kv - s[j];
            d1 = kv - s[j + STEP];
            a0[j] = fmaf(d0, d0, m0);
            a1[j] = fmaf(d1, d1, m1);
            dg0 = up0;                            // renamed away by unroll
            dg1 = up1;
        }
    }

    // out[b, c*F + f, w]: coalesced in w (two adjacent elements per thread)
    const size_t o = ((size_t)bc * Ff + f) * NWIN + g0;
    out[o] = a0[PROC - 1];
    if (g0 + 1 < NWIN) out[o + 1] = a1[PROC - 1];
}

extern "C" void kernel_launch(void* const* d_in, const int* in_sizes, int n_in,
                              void* d_out, int out_size)
{
    const float* x       = (const float*)d_in[0];   // (8, 8, 4096) f32
    const float* kernels = (const float*)d_in[1];   // (32, 10) f32
    float*       out     = (float*)d_out;           // (8, 256, 815) f32

    (void)in_sizes; (void)n_in; (void)out_size;

    dim3 grid(NTILE, Ff, 8 * Cc);   // (2, 32, 64)
    dtw_kernel<<<grid, WPB>>>(x, kernels, out);
}

// round 9
// speedup vs baseline: 1.0512x; 1.0512x over previous
#include <cuda_runtime.h>
#include <cuda_bf16.h>

// Problem constants (fixed by the reference)
#define Cc    8
#define Ll    4096
#define Ff    32
#define Kk    10
#define PROC  20
#define STEP  5
#define NWIN  815          // == CHAN_OUT, no pad region
#define WPB   416          // threads per block (13 warps); 2 windows/thread
#define WINPB 832          // window slots per block (covers all 815, 2% waste)

// Shared x tile: covers WINPB windows -> WINPB*STEP + (PROC-STEP) = 4175 floats
#define SXN (WINPB * STEP + PROC - STEP)

// Exact 3-way float min for NONNEGATIVE floats via DPX reinterpretation.
__device__ __forceinline__ float fmin3_nonneg(float a, float b, float c)
{
    return __int_as_float(__vimin3_s32(__float_as_int(a),
                                       __float_as_int(b),
                                       __float_as_int(c)));
}

__global__ __launch_bounds__(WPB, 2)
void dtw_kernel(const float* __restrict__ x,
                const float* __restrict__ kernels,
                float* __restrict__ out)
{
    const int f   = blockIdx.x;           // filter  [0, Ff)
    const int bc  = blockIdx.y;           // b*C + c [0, 64)
    const int tid = threadIdx.x;

    __shared__ float sx[SXN];

    // Cooperative, coalesced load of the whole channel for this (b,c)
    const float* xc = x + (size_t)bc * Ll;
    #pragma unroll
    for (int i = tid; i < SXN; i += WPB) {
        sx[i] = (i < Ll) ? xc[i] : 0.0f;
    }
    __syncthreads();

    // This thread owns adjacent windows g0 = 2*tid and g0+1.
    const int g0 = 2 * tid;
    if (g0 >= NWIN) return;               // only 8 threads exit; no syncs below

    // Kernel taps: warp-uniform addresses -> broadcast loads, L1-resident
    float ker[Kk];
    #pragma unroll
    for (int i = 0; i < Kk; i++) ker[i] = __ldg(&kernels[f * Kk + i]);

    // 25-float span covers BOTH windows: w0[j] = s[j], w1[j] = s[j+5].
    float s[PROC + STEP];
    #pragma unroll
    for (int j = 0; j < PROC + STEP; j++) s[j] = sx[g0 * STEP + j];

    // Two independent DTW tables, interleaved for ILP=2. Fully unrolled:
    // register renaming kills all rotation MOVs.
    float a0[PROC], a1[PROC];

    // Row 0: cumulative sum of squared diffs
    {
        const float k0 = ker[0];
        float d0 = k0 - s[0];
        float d1 = k0 - s[STEP];
        a0[0] = d0 * d0;
        a1[0] = d1 * d1;
        #pragma unroll
        for (int j = 1; j < PROC; j++) {
            d0 = k0 - s[j];
            d1 = k0 - s[j + STEP];
            a0[j] = fmaf(d0, d0, a0[j - 1]);
            a1[j] = fmaf(d1, d1, a1[j - 1]);
        }
    }

    // Rows 1..K-1. pmin/3-way min off the left-dependency chain:
    // serial path per cell = min + FFMA; two chains overlap across windows.
    #pragma unroll
    for (int i = 1; i < Kk; i++) {
        const float kv = ker[i];
        float dg0 = a0[0];
        float dg1 = a1[0];
        float d0 = kv - s[0];
        float d1 = kv - s[STEP];
        a0[0] = fmaf(d0, d0, a0[0]);
        a1[0] = fmaf(d1, d1, a1[0]);
        #pragma unroll
        for (int j = 1; j < PROC; j++) {
            const float up0 = a0[j];
            const float up1 = a1[j];
            const float m0  = fmin3_nonneg(a0[j - 1], up0, dg0);
            const float m1  = fmin3_nonneg(a1[j - 1], up1, dg1);
            d0 = kv - s[j];
            d1 = kv - s[j + STEP];
            a0[j] = fmaf(d0, d0, m0);
            a1[j] = fmaf(d1, d1, m1);
            dg0 = up0;                            // renamed away by unroll
            dg1 = up1;
        }
    }

    // out[b, c*F + f, w]: coalesced in w (two adjacent elements per thread)
    const size_t o = ((size_t)bc * Ff + f) * NWIN + g0;
    out[o] = a0[PROC - 1];
    if (g0 + 1 < NWIN) out[o + 1] = a1[PROC - 1];
}

extern "C" void kernel_launch(void* const* d_in, const int* in_sizes, int n_in,
                              void* d_out, int out_size)
{
    const float* x       = (const float*)d_in[0];   // (8, 8, 4096) f32
    const float* kernels = (const float*)d_in[1];   // (32, 10) f32
    float*       out     = (float*)d_out;           // (8, 256, 815) f32

    (void)in_sizes; (void)n_in; (void)out_size;

    dim3 grid(Ff, 8 * Cc);   // (32, 64) -> 2048 blocks
    dtw_kernel<<<grid, WPB>>>(x, kernels, out);
}

// round 10
// speedup vs baseline: 1.0581x; 1.0065x over previous
#include <cuda_runtime.h>
#include <cuda_bf16.h>

// Problem constants (fixed by the reference)
#define Cc    8
#define Ll    4096
#define Ff    32
#define Kk    10
#define PROC  20
#define STEP  5
#define NWIN  815          // == CHAN_OUT, no pad region
#define WPB   416          // threads per block (13 warps); 2 windows/thread
#define WINPB 832          // window slots per block (covers all 815, 2% waste)

// Shared x tile: covers WINPB windows -> WINPB*STEP + (PROC-STEP) = 4175 floats
#define SXN (WINPB * STEP + PROC - STEP)

// Exact 3-way float min for NONNEGATIVE floats via DPX (single VIMNMX3):
// IEEE nonneg floats order identically to their int bit patterns.
__device__ __forceinline__ float fmin3_nonneg(float a, float b, float c)
{
    return __int_as_float(__vimin3_s32(__float_as_int(a),
                                       __float_as_int(b),
                                       __float_as_int(c)));
}

__global__ __launch_bounds__(WPB, 3)
void dtw_kernel(const float* __restrict__ x,
                const float* __restrict__ kernels,
                float* __restrict__ out)
{
    const int f   = blockIdx.x;           // filter  [0, Ff)
    const int bc  = blockIdx.y;           // b*C + c [0, 64)
    const int tid = threadIdx.x;

    __shared__ float sx[SXN];

    // Cooperative, coalesced load of the whole channel for this (b,c)
    const float* xc = x + (size_t)bc * Ll;
    #pragma unroll
    for (int i = tid; i < SXN; i += WPB) {
        sx[i] = (i < Ll) ? xc[i] : 0.0f;
    }
    __syncthreads();

    // This thread owns adjacent windows g0 = 2*tid and g0+1.
    const int g0 = 2 * tid;
    if (g0 >= NWIN) return;               // only 8 threads exit; no syncs below

    // Kernel taps: warp-uniform addresses -> broadcast loads, L1-resident
    float ker[Kk];
    #pragma unroll
    for (int i = 0; i < Kk; i++) ker[i] = __ldg(&kernels[f * Kk + i]);

    // 25-float span covers BOTH windows: w0[j] = s[j], w1[j] = s[j+5].
    float s[PROC + STEP];
    #pragma unroll
    for (int j = 0; j < PROC + STEP; j++) s[j] = sx[g0 * STEP + j];

    // Two independent DTW tables, interleaved for ILP=2. Fully unrolled:
    // register renaming kills all rotation MOVs.
    float a0[PROC], a1[PROC];

    // Row 0: cumulative sum of squared diffs
    {
        const float k0 = ker[0];
        float d0 = k0 - s[0];
        float d1 = k0 - s[STEP];
        a0[0] = d0 * d0;
        a1[0] = d1 * d1;
        #pragma unroll
        for (int j = 1; j < PROC; j++) {
            d0 = k0 - s[j];
            d1 = k0 - s[j + STEP];
            a0[j] = fmaf(d0, d0, a0[j - 1]);
            a1[j] = fmaf(d1, d1, a1[j - 1]);
        }
    }

    // Rows 1..K-1. Single DPX 3-way min per cell (values >= 0 so int-ordered
    // min is exact); serial path per cell = VIMNMX3 + FFMA.
    #pragma unroll
    for (int i = 1; i < Kk; i++) {
        const float kv = ker[i];
        float dg0 = a0[0];
        float dg1 = a1[0];
        float d0 = kv - s[0];
        float d1 = kv - s[STEP];
        a0[0] = fmaf(d0, d0, a0[0]);
        a1[0] = fmaf(d1, d1, a1[0]);
        #pragma unroll
        for (int j = 1; j < PROC; j++) {
            const float up0 = a0[j];
            const float up1 = a1[j];
            const float m0  = fmin3_nonneg(a0[j - 1], up0, dg0);
            const float m1  = fmin3_nonneg(a1[j - 1], up1, dg1);
            d0 = kv - s[j];
            d1 = kv - s[j + STEP];
            a0[j] = fmaf(d0, d0, m0);
            a1[j] = fmaf(d1, d1, m1);
            dg0 = up0;                            // renamed away by unroll
            dg1 = up1;
        }
    }

    // out[b, c*F + f, w]: coalesced in w (two adjacent elements per thread)
    const size_t o = ((size_t)bc * Ff + f) * NWIN + g0;
    out[o] = a0[PROC - 1];
    if (g0 + 1 < NWIN) out[o + 1] = a1[PROC - 1];
}

extern "C" void kernel_launch(void* const* d_in, const int* in_sizes, int n_in,
                              void* d_out, int out_size)
{
    const float* x       = (const float*)d_in[0];   // (8, 8, 4096) f32
    const float* kernels = (const float*)d_in[1];   // (32, 10) f32
    float*       out     = (float*)d_out;           // (8, 256, 815) f32

    (void)in_sizes; (void)n_in; (void)out_size;

    dim3 grid(Ff, 8 * Cc);   // (32, 64) -> 2048 blocks
    dtw_kernel<<<grid, WPB>>>(x, kernels, out);
}